// round 1
// baseline (speedup 1.0000x reference)
#include <cuda_runtime.h>
#include <math.h>

#define S_   256
#define B_   512
#define H_   512
#define E_   256
#define L_   4
#define OUT_ 128

// ---------------- scratch (no allocs allowed) ----------------
__device__ float g_Wh[B_ * H_];            // [B,H]
__device__ float g_rnn[B_ * (H_ + E_)];    // [B, H+E]  (context | emb)
__device__ float g_energy[S_ * B_];        // [S,B] energy -> attention in place
__device__ float g_gi[B_ * 3 * H_];        // [B,3H]
__device__ float g_gh[B_ * 3 * H_];        // [B,3H]

// ---------------- generic tiled SGEMM: C[M,N] = A[M,K] @ W[N,K]^T + bias ----------------
// BM=BN=64, BK=16, 256 threads, 4x4 thread tile. M,N multiples of 64 (N=128 ok), K mult of 16.
__global__ void gemm_bias_kernel(const float* __restrict__ A,
                                 const float* __restrict__ W,
                                 const float* __restrict__ bias,
                                 float* __restrict__ C,
                                 int M, int N, int K)
{
    __shared__ float As[16][64];
    __shared__ float Ws[16][64];
    const int tid = threadIdx.x;
    const int tx = tid & 15;
    const int ty = tid >> 4;
    const int m0 = blockIdx.y * 64;
    const int n0 = blockIdx.x * 64;

    float acc[4][4] = {};

    for (int kt = 0; kt < K; kt += 16) {
        {
            int m  = tid >> 2;
            int kq = (tid & 3) * 4;
            float4 v = *(const float4*)&A[(size_t)(m0 + m) * K + kt + kq];
            As[kq + 0][m] = v.x; As[kq + 1][m] = v.y;
            As[kq + 2][m] = v.z; As[kq + 3][m] = v.w;
        }
        {
            int n  = tid >> 2;
            int kq = (tid & 3) * 4;
            float4 v = *(const float4*)&W[(size_t)(n0 + n) * K + kt + kq];
            Ws[kq + 0][n] = v.x; Ws[kq + 1][n] = v.y;
            Ws[kq + 2][n] = v.z; Ws[kq + 3][n] = v.w;
        }
        __syncthreads();
#pragma unroll
        for (int k = 0; k < 16; k++) {
            float4 a = *(float4*)&As[k][ty * 4];
            float4 b = *(float4*)&Ws[k][tx * 4];
            float av[4] = {a.x, a.y, a.z, a.w};
            float bv[4] = {b.x, b.y, b.z, b.w};
#pragma unroll
            for (int i = 0; i < 4; i++)
#pragma unroll
                for (int j = 0; j < 4; j++)
                    acc[i][j] = fmaf(av[i], bv[j], acc[i][j]);
        }
        __syncthreads();
    }

#pragma unroll
    for (int i = 0; i < 4; i++) {
        int m = m0 + ty * 4 + i;
#pragma unroll
        for (int j = 0; j < 4; j++) {
            int n = n0 + tx * 4 + j;
            C[(size_t)m * N + n] = acc[i][j] + bias[n];
        }
    }
}

// ---------------- fused energy kernel ----------------
// energy[s,b] = sum_o aw[o]*tanh( (Es[s,b,:]@Uw[o,:]) + Ub[o] + Wh[b,o] ) + ab
// Block: 64 rows of flattened (s*B+b), loops over 4 chunks of 128 output cols.
// 256 threads (16x16), thread tile 4 rows x 8 cols, BK=16.
__global__ void energy_kernel(const float* __restrict__ Es,
                              const float* __restrict__ Uw,
                              const float* __restrict__ Ub,
                              const float* __restrict__ Wh,
                              const float* __restrict__ aw,
                              const float* __restrict__ ab,
                              float* __restrict__ energy)
{
    __shared__ float As[16][64];
    __shared__ float Bs[16][128];
    const int tid = threadIdx.x;
    const int tx = tid & 15;
    const int ty = tid >> 4;
    const int r0 = blockIdx.x * 64;

    float eacc[4] = {0.f, 0.f, 0.f, 0.f};

    for (int oc = 0; oc < 4; oc++) {
        const int ob = oc * 128;
        float acc[4][8] = {};
        for (int kt = 0; kt < H_; kt += 16) {
            {
                int m  = tid >> 2;
                int kq = (tid & 3) * 4;
                float4 v = *(const float4*)&Es[(size_t)(r0 + m) * H_ + kt + kq];
                As[kq + 0][m] = v.x; As[kq + 1][m] = v.y;
                As[kq + 2][m] = v.z; As[kq + 3][m] = v.w;
            }
            {
                int o  = tid >> 1;
                int kq = (tid & 1) * 8;
                float4 v0 = *(const float4*)&Uw[(size_t)(ob + o) * H_ + kt + kq];
                float4 v1 = *(const float4*)&Uw[(size_t)(ob + o) * H_ + kt + kq + 4];
                Bs[kq + 0][o] = v0.x; Bs[kq + 1][o] = v0.y;
                Bs[kq + 2][o] = v0.z; Bs[kq + 3][o] = v0.w;
                Bs[kq + 4][o] = v1.x; Bs[kq + 5][o] = v1.y;
                Bs[kq + 6][o] = v1.z; Bs[kq + 7][o] = v1.w;
            }
            __syncthreads();
#pragma unroll
            for (int k = 0; k < 16; k++) {
                float4 a  = *(float4*)&As[k][ty * 4];
                float4 b0 = *(float4*)&Bs[k][tx * 8];
                float4 b1 = *(float4*)&Bs[k][tx * 8 + 4];
                float av[4] = {a.x, a.y, a.z, a.w};
                float bv[8] = {b0.x, b0.y, b0.z, b0.w, b1.x, b1.y, b1.z, b1.w};
#pragma unroll
                for (int i = 0; i < 4; i++)
#pragma unroll
                    for (int j = 0; j < 8; j++)
                        acc[i][j] = fmaf(av[i], bv[j], acc[i][j]);
            }
            __syncthreads();
        }
        // tanh-weighted reduction for this output-column chunk
#pragma unroll
        for (int i = 0; i < 4; i++) {
            int r = r0 + ty * 4 + i;
            int b = r & (B_ - 1);
            float e = 0.f;
#pragma unroll
            for (int j = 0; j < 8; j++) {
                int o = ob + tx * 8 + j;
                e += tanhf(acc[i][j] + Ub[o] + Wh[(size_t)b * H_ + o]) * aw[o];
            }
            eacc[i] += e;
        }
    }

    // reduce across the 16 tx lanes (tid = ty*16+tx -> tx lanes are contiguous in half-warp)
#pragma unroll
    for (int i = 0; i < 4; i++) {
        float e = eacc[i];
#pragma unroll
        for (int off = 8; off; off >>= 1)
            e += __shfl_xor_sync(0xffffffffu, e, off);
        if (tx == 0) {
            int r = r0 + ty * 4 + i;
            energy[r] = e + ab[0];
        }
    }
}

// ---------------- softmax over S (one block per b) ----------------
__global__ void softmax_kernel(float* __restrict__ energy)
{
    __shared__ float red[S_];
    const int b = blockIdx.x;
    const int s = threadIdx.x;
    float v = energy[s * B_ + b];
    red[s] = v;
    __syncthreads();
    for (int off = S_ / 2; off; off >>= 1) {
        if (s < off) red[s] = fmaxf(red[s], red[s + off]);
        __syncthreads();
    }
    float m = red[0];
    __syncthreads();
    float ex = __expf(v - m);
    red[s] = ex;
    __syncthreads();
    for (int off = S_ / 2; off; off >>= 1) {
        if (s < off) red[s] += red[s + off];
        __syncthreads();
    }
    energy[s * B_ + b] = ex / red[0];
}

// ---------------- context: rnn[b, 0:H] = sum_s att[s,b] * Es[s,b,:] ----------------
__global__ void context_kernel(const float* __restrict__ att,
                               const float* __restrict__ Es,
                               float* __restrict__ rnn)
{
    const int b = blockIdx.y;
    const int h = blockIdx.x * 128 + threadIdx.x;
    float a0 = 0.f, a1 = 0.f, a2 = 0.f, a3 = 0.f;
#pragma unroll 4
    for (int s = 0; s < S_; s += 4) {
        a0 = fmaf(att[(s + 0) * B_ + b], Es[((size_t)(s + 0) * B_ + b) * H_ + h], a0);
        a1 = fmaf(att[(s + 1) * B_ + b], Es[((size_t)(s + 1) * B_ + b) * H_ + h], a1);
        a2 = fmaf(att[(s + 2) * B_ + b], Es[((size_t)(s + 2) * B_ + b) * H_ + h], a2);
        a3 = fmaf(att[(s + 3) * B_ + b], Es[((size_t)(s + 3) * B_ + b) * H_ + h], a3);
    }
    rnn[(size_t)b * (H_ + E_) + h] = (a0 + a1) + (a2 + a3);
}

// ---------------- embedding gather: rnn[b, H:H+E] = emb[x[b]] ----------------
__global__ void emb_kernel(const int* __restrict__ x,
                           const float* __restrict__ emb,
                           float* __restrict__ rnn)
{
    const int b = blockIdx.x;
    const int e = threadIdx.x;
    rnn[(size_t)b * (H_ + E_) + H_ + e] = emb[(size_t)x[b] * E_ + e];
}

// ---------------- GRU gate fusion ----------------
__global__ void gate_kernel(const float* __restrict__ gi,
                            const float* __restrict__ gh,
                            const float* __restrict__ hprev,
                            float* __restrict__ hnew)
{
    const int idx = blockIdx.x * 256 + threadIdx.x;  // over B*H
    const int b = idx >> 9;
    const int o = idx & (H_ - 1);
    const float* gib = gi + (size_t)b * 3 * H_;
    const float* ghb = gh + (size_t)b * 3 * H_;
    float ir = gib[o], iz = gib[o + H_], inn = gib[o + 2 * H_];
    float hr = ghb[o], hz = ghb[o + H_], hn = ghb[o + 2 * H_];
    float r = 1.f / (1.f + __expf(-(ir + hr)));
    float z = 1.f / (1.f + __expf(-(iz + hz)));
    float n = tanhf(fmaf(r, hn, inn));
    float h = hprev[idx];
    hnew[idx] = fmaf(z, h - n, n);   // (1-z)*n + z*h
}

// ---------------- launch ----------------
extern "C" void kernel_launch(void* const* d_in, const int* in_sizes, int n_in,
                              void* d_out, int out_size)
{
    const int*   x      = (const int*)  d_in[0];
    const float* Es     = (const float*)d_in[1];
    const float* hidden = (const float*)d_in[2];
    // d_in[3] = cell (unused by reference)
    const float* emb    = (const float*)d_in[4];
    const float* Uw     = (const float*)d_in[5];
    const float* Ub     = (const float*)d_in[6];
    const float* Ww     = (const float*)d_in[7];
    const float* Wb     = (const float*)d_in[8];
    const float* aw     = (const float*)d_in[9];
    const float* ab     = (const float*)d_in[10];
    const float* w_ih0  = (const float*)d_in[11];
    const float* w_hh0  = (const float*)d_in[12];
    const float* b_ih0  = (const float*)d_in[13];
    const float* b_hh0  = (const float*)d_in[14];
    const float* w_ih_r = (const float*)d_in[15];
    const float* w_hh_r = (const float*)d_in[16];
    const float* b_ih_r = (const float*)d_in[17];
    const float* b_hh_r = (const float*)d_in[18];
    const float* fcw    = (const float*)d_in[19];
    const float* fcb    = (const float*)d_in[20];

    float* out     = (float*)d_out;
    float* pred    = out;               // [B, OUT]
    float* hid_out = out + B_ * OUT_;   // [L, B, H]

    float *Wh, *rnn, *energy, *gi, *gh;
    cudaGetSymbolAddress((void**)&Wh,     g_Wh);
    cudaGetSymbolAddress((void**)&rnn,    g_rnn);
    cudaGetSymbolAddress((void**)&energy, g_energy);
    cudaGetSymbolAddress((void**)&gi,     g_gi);
    cudaGetSymbolAddress((void**)&gh,     g_gh);

    // 1) Wh = hidden[-1] @ Ww^T + Wb
    gemm_bias_kernel<<<dim3(H_ / 64, B_ / 64), 256>>>(
        hidden + (size_t)(L_ - 1) * B_ * H_, Ww, Wb, Wh, B_, H_, H_);

    // 2) embedding gather (independent)
    emb_kernel<<<B_, E_>>>(x, emb, rnn);

    // 3) fused energy (big GEMM + tanh + aw-reduction)
    energy_kernel<<<(S_ * B_) / 64, 256>>>(Es, Uw, Ub, Wh, aw, ab, energy);

    // 4) softmax over S
    softmax_kernel<<<B_, S_>>>(energy);

    // 5) context -> rnn[:, 0:H]
    context_kernel<<<dim3(H_ / 128, B_), 128>>>(energy, Es, rnn);

    // 6) GRU layer 0
    gemm_bias_kernel<<<dim3(3 * H_ / 64, B_ / 64), 256>>>(
        rnn, w_ih0, b_ih0, gi, B_, 3 * H_, H_ + E_);
    gemm_bias_kernel<<<dim3(3 * H_ / 64, B_ / 64), 256>>>(
        hidden, w_hh0, b_hh0, gh, B_, 3 * H_, H_);
    gate_kernel<<<(B_ * H_) / 256, 256>>>(gi, gh, hidden, hid_out);

    // 7) GRU layers 1..3
    for (int l = 1; l < L_; l++) {
        const float* wih = w_ih_r + (size_t)(l - 1) * 3 * H_ * H_;
        const float* whh = w_hh_r + (size_t)(l - 1) * 3 * H_ * H_;
        const float* bih = b_ih_r + (size_t)(l - 1) * 3 * H_;
        const float* bhh = b_hh_r + (size_t)(l - 1) * 3 * H_;
        const float* hin = hid_out + (size_t)(l - 1) * B_ * H_;
        const float* hpv = hidden + (size_t)l * B_ * H_;
        gemm_bias_kernel<<<dim3(3 * H_ / 64, B_ / 64), 256>>>(
            hin, wih, bih, gi, B_, 3 * H_, H_);
        gemm_bias_kernel<<<dim3(3 * H_ / 64, B_ / 64), 256>>>(
            hpv, whh, bhh, gh, B_, 3 * H_, H_);
        gate_kernel<<<(B_ * H_) / 256, 256>>>(gi, gh, hpv, hid_out + (size_t)l * B_ * H_);
    }

    // 8) predictions = h_last @ fcw^T + fcb
    gemm_bias_kernel<<<dim3(OUT_ / 64, B_ / 64), 256>>>(
        hid_out + (size_t)(L_ - 1) * B_ * H_, fcw, fcb, pred, B_, OUT_, H_);
}

// round 2
// speedup vs baseline: 3.6236x; 3.6236x over previous
#include <cuda_runtime.h>
#include <math.h>
#include <stdint.h>

#define S_   256
#define B_   512
#define H_   512
#define E_   256
#define L_   4
#define OUT_ 128

#define TPAD 20   // smem row stride (16 k + 4 pad) -> conflict-free tf32 frag loads

// ---------------- scratch (no allocs allowed) ----------------
__device__ float g_Wh[B_ * H_];
__device__ float g_rnn[B_ * (H_ + E_)];
__device__ float g_energy[S_ * B_];
__device__ float g_gi[B_ * 3 * H_];
__device__ float g_gh[B_ * 3 * H_];

// ---------------- tf32 helpers ----------------
__device__ __forceinline__ uint32_t f2tf(float f) {
    uint32_t u;
    asm("cvt.rna.tf32.f32 %0, %1;" : "=r"(u) : "f"(f));
    return u;
}

__device__ __forceinline__ void mma8(float* c, const uint32_t* a, const uint32_t* b) {
    asm volatile(
        "mma.sync.aligned.m16n8k8.row.col.f32.tf32.tf32.f32 "
        "{%0,%1,%2,%3}, {%4,%5,%6,%7}, {%8,%9}, {%0,%1,%2,%3};\n"
        : "+f"(c[0]), "+f"(c[1]), "+f"(c[2]), "+f"(c[3])
        : "r"(a[0]), "r"(a[1]), "r"(a[2]), "r"(a[3]), "r"(b[0]), "r"(b[1]));
}

// Compute one 16-deep K tile: block tile 128x128, warp tile 32x64 (wm 0..3, wn 0..1)
__device__ __forceinline__ void compute_tile(float acc[2][8][4],
                                             const uint32_t* As, const uint32_t* Ws,
                                             int wm, int wn, int g, int tg) {
#pragma unroll
    for (int ks = 0; ks < 16; ks += 8) {
        uint32_t af[2][4], bf[8][2];
#pragma unroll
        for (int mi = 0; mi < 2; mi++) {
            int rb = wm * 32 + mi * 16;
            af[mi][0] = As[(rb + g) * TPAD + ks + tg];
            af[mi][1] = As[(rb + g + 8) * TPAD + ks + tg];
            af[mi][2] = As[(rb + g) * TPAD + ks + tg + 4];
            af[mi][3] = As[(rb + g + 8) * TPAD + ks + tg + 4];
        }
#pragma unroll
        for (int ni = 0; ni < 8; ni++) {
            int nb = wn * 64 + ni * 8;
            bf[ni][0] = Ws[(nb + g) * TPAD + ks + tg];
            bf[ni][1] = Ws[(nb + g) * TPAD + ks + tg + 4];
        }
#pragma unroll
        for (int mi = 0; mi < 2; mi++)
#pragma unroll
            for (int ni = 0; ni < 8; ni++)
                mma8(acc[mi][ni], af[mi], bf[ni]);
    }
}

// Full K mainloop: loads A rows [row0,row0+128) and W rows [n0,n0+128) of
// row-major [*,K] matrices, converts to tf32 in smem, register-prefetches.
__device__ __forceinline__ void gemm_mainloop(float acc[2][8][4],
                                              const float* __restrict__ A,
                                              const float* __restrict__ W,
                                              int row0, int n0, int K,
                                              uint32_t* As, uint32_t* Ws,
                                              int tid, int wm, int wn, int g, int tg) {
#pragma unroll
    for (int it = 0; it < 2; it++) {
        int idx = it * 256 + tid;
        int m = idx >> 2;
        int kq = (idx & 3) * 4;
        float4 v = *(const float4*)&A[(size_t)(row0 + m) * K + kq];
        uint4 u = {f2tf(v.x), f2tf(v.y), f2tf(v.z), f2tf(v.w)};
        *(uint4*)&As[m * TPAD + kq] = u;
        float4 w = *(const float4*)&W[(size_t)(n0 + m) * K + kq];
        uint4 uw = {f2tf(w.x), f2tf(w.y), f2tf(w.z), f2tf(w.w)};
        *(uint4*)&Ws[m * TPAD + kq] = uw;
    }
    __syncthreads();
    const int nk = K / 16;
    for (int kt = 1; kt <= nk; kt++) {
        float4 va[2], vw[2];
        if (kt < nk) {
#pragma unroll
            for (int it = 0; it < 2; it++) {
                int idx = it * 256 + tid;
                int m = idx >> 2;
                int kq = (idx & 3) * 4;
                va[it] = *(const float4*)&A[(size_t)(row0 + m) * K + kt * 16 + kq];
                vw[it] = *(const float4*)&W[(size_t)(n0 + m) * K + kt * 16 + kq];
            }
        }
        compute_tile(acc, As, Ws, wm, wn, g, tg);
        __syncthreads();
        if (kt < nk) {
#pragma unroll
            for (int it = 0; it < 2; it++) {
                int idx = it * 256 + tid;
                int m = idx >> 2;
                int kq = (idx & 3) * 4;
                uint4 u = {f2tf(va[it].x), f2tf(va[it].y), f2tf(va[it].z), f2tf(va[it].w)};
                *(uint4*)&As[m * TPAD + kq] = u;
                uint4 uw = {f2tf(vw[it].x), f2tf(vw[it].y), f2tf(vw[it].z), f2tf(vw[it].w)};
                *(uint4*)&Ws[m * TPAD + kq] = uw;
            }
            __syncthreads();
        }
    }
}

// ---------------- fused energy kernel (tensor-core) ----------------
// energy[r] = ab + sum_o aw[o]*tanh( Es[r,:]@Uw[o,:] + Ub[o] + Wh[r&511, o] )
__global__ __launch_bounds__(256, 2) void energy_mma_kernel(
    const float* __restrict__ Es, const float* __restrict__ Uw,
    const float* __restrict__ Ub, const float* __restrict__ Wh,
    const float* __restrict__ aw, const float* __restrict__ ab,
    float* __restrict__ energy) {
    __shared__ __align__(16) uint32_t As[128 * TPAD];
    __shared__ __align__(16) uint32_t Ws[128 * TPAD];
    __shared__ float esum[128];

    const int tid = threadIdx.x;
    const int lane = tid & 31, warp = tid >> 5;
    const int g = lane >> 2, tg = lane & 3;
    const int wm = warp >> 1, wn = warp & 1;
    const int r0 = blockIdx.x * 128;

    if (tid < 128) esum[tid] = 0.f;
    __syncthreads();

    for (int nc = 0; nc < 4; nc++) {
        const int n0 = nc * 128;
        float acc[2][8][4] = {};
        gemm_mainloop(acc, Es, Uw, r0, n0, H_, As, Ws, tid, wm, wn, g, tg);

        float rsum[4];
#pragma unroll
        for (int mi = 0; mi < 2; mi++)
#pragma unroll
            for (int half = 0; half < 2; half++) {
                int row = wm * 32 + mi * 16 + g + half * 8;
                int b = (r0 + row) & (B_ - 1);
                float v = 0.f;
#pragma unroll
                for (int ni = 0; ni < 8; ni++) {
                    int col0 = n0 + wn * 64 + ni * 8 + tg * 2;
                    float p0 = acc[mi][ni][half * 2 + 0] + Ub[col0] + Wh[(size_t)b * H_ + col0];
                    float p1 = acc[mi][ni][half * 2 + 1] + Ub[col0 + 1] + Wh[(size_t)b * H_ + col0 + 1];
                    v += tanhf(p0) * aw[col0] + tanhf(p1) * aw[col0 + 1];
                }
                rsum[mi * 2 + half] = v;
            }
#pragma unroll
        for (int i = 0; i < 4; i++) {
            float v = rsum[i];
            v += __shfl_xor_sync(0xffffffffu, v, 1);
            v += __shfl_xor_sync(0xffffffffu, v, 2);
            if (tg == 0) {
                int mi = i >> 1, half = i & 1;
                int row = wm * 32 + mi * 16 + g + half * 8;
                atomicAdd(&esum[row], v);
            }
        }
        __syncthreads();
    }
    if (tid < 128) energy[r0 + tid] = esum[tid] + ab[0];
}

// ---------------- generic tensor-core GEMM (+bias), 2 jobs via gridDim.z ----------------
__global__ __launch_bounds__(256, 2) void gemm2_kernel(
    const float* __restrict__ A0, const float* __restrict__ W0,
    const float* __restrict__ bias0, float* __restrict__ C0, int K0,
    const float* __restrict__ A1, const float* __restrict__ W1,
    const float* __restrict__ bias1, float* __restrict__ C1, int K1,
    int N) {
    __shared__ __align__(16) uint32_t As[128 * TPAD];
    __shared__ __align__(16) uint32_t Ws[128 * TPAD];

    const float *A, *W, *bias;
    float* C;
    int K;
    if (blockIdx.z == 0) { A = A0; W = W0; bias = bias0; C = C0; K = K0; }
    else                 { A = A1; W = W1; bias = bias1; C = C1; K = K1; }

    const int tid = threadIdx.x;
    const int lane = tid & 31, warp = tid >> 5;
    const int g = lane >> 2, tg = lane & 3;
    const int wm = warp >> 1, wn = warp & 1;
    const int m0 = blockIdx.y * 128;
    const int n0 = blockIdx.x * 128;

    float acc[2][8][4] = {};
    gemm_mainloop(acc, A, W, m0, n0, K, As, Ws, tid, wm, wn, g, tg);

#pragma unroll
    for (int mi = 0; mi < 2; mi++)
#pragma unroll
        for (int half = 0; half < 2; half++) {
            int row = m0 + wm * 32 + mi * 16 + g + half * 8;
#pragma unroll
            for (int ni = 0; ni < 8; ni++) {
                int col = n0 + wn * 64 + ni * 8 + tg * 2;
                float2 o;
                o.x = acc[mi][ni][half * 2 + 0] + bias[col];
                o.y = acc[mi][ni][half * 2 + 1] + bias[col + 1];
                *(float2*)&C[(size_t)row * N + col] = o;
            }
        }
}

// ---------------- softmax over S (one block per b) ----------------
__global__ void softmax_kernel(float* __restrict__ energy) {
    __shared__ float red[S_];
    const int b = blockIdx.x;
    const int s = threadIdx.x;
    float v = energy[s * B_ + b];
    red[s] = v;
    __syncthreads();
    for (int off = S_ / 2; off; off >>= 1) {
        if (s < off) red[s] = fmaxf(red[s], red[s + off]);
        __syncthreads();
    }
    float m = red[0];
    __syncthreads();
    float ex = __expf(v - m);
    red[s] = ex;
    __syncthreads();
    for (int off = S_ / 2; off; off >>= 1) {
        if (s < off) red[s] += red[s + off];
        __syncthreads();
    }
    energy[s * B_ + b] = ex / red[0];
}

// ---------------- context: rnn[b, 0:H] = sum_s att[s,b] * Es[s,b,:] ----------------
__global__ void context_kernel(const float* __restrict__ att,
                               const float* __restrict__ Es,
                               float* __restrict__ rnn) {
    const int b = blockIdx.y;
    const int h = blockIdx.x * 128 + threadIdx.x;
    float a0 = 0.f, a1 = 0.f, a2 = 0.f, a3 = 0.f;
#pragma unroll 4
    for (int s = 0; s < S_; s += 4) {
        a0 = fmaf(att[(s + 0) * B_ + b], Es[((size_t)(s + 0) * B_ + b) * H_ + h], a0);
        a1 = fmaf(att[(s + 1) * B_ + b], Es[((size_t)(s + 1) * B_ + b) * H_ + h], a1);
        a2 = fmaf(att[(s + 2) * B_ + b], Es[((size_t)(s + 2) * B_ + b) * H_ + h], a2);
        a3 = fmaf(att[(s + 3) * B_ + b], Es[((size_t)(s + 3) * B_ + b) * H_ + h], a3);
    }
    rnn[(size_t)b * (H_ + E_) + h] = (a0 + a1) + (a2 + a3);
}

// ---------------- embedding gather ----------------
__global__ void emb_kernel(const int* __restrict__ x,
                           const float* __restrict__ emb,
                           float* __restrict__ rnn) {
    const int b = blockIdx.x;
    const int e = threadIdx.x;
    rnn[(size_t)b * (H_ + E_) + H_ + e] = emb[(size_t)x[b] * E_ + e];
}

// ---------------- GRU gate fusion ----------------
__global__ void gate_kernel(const float* __restrict__ gi,
                            const float* __restrict__ gh,
                            const float* __restrict__ hprev,
                            float* __restrict__ hnew) {
    const int idx = blockIdx.x * 256 + threadIdx.x;  // over B*H
    const int b = idx >> 9;
    const int o = idx & (H_ - 1);
    const float* gib = gi + (size_t)b * 3 * H_;
    const float* ghb = gh + (size_t)b * 3 * H_;
    float ir = gib[o], iz = gib[o + H_], inn = gib[o + 2 * H_];
    float hr = ghb[o], hz = ghb[o + H_], hn = ghb[o + 2 * H_];
    float r = 1.f / (1.f + __expf(-(ir + hr)));
    float z = 1.f / (1.f + __expf(-(iz + hz)));
    float n = tanhf(fmaf(r, hn, inn));
    float h = hprev[idx];
    hnew[idx] = fmaf(z, h - n, n);   // (1-z)*n + z*h
}

// ---------------- launch ----------------
extern "C" void kernel_launch(void* const* d_in, const int* in_sizes, int n_in,
                              void* d_out, int out_size) {
    const int*   x      = (const int*)  d_in[0];
    const float* Es     = (const float*)d_in[1];
    const float* hidden = (const float*)d_in[2];
    const float* emb    = (const float*)d_in[4];
    const float* Uw     = (const float*)d_in[5];
    const float* Ub     = (const float*)d_in[6];
    const float* Ww     = (const float*)d_in[7];
    const float* Wb     = (const float*)d_in[8];
    const float* aw     = (const float*)d_in[9];
    const float* ab     = (const float*)d_in[10];
    const float* w_ih0  = (const float*)d_in[11];
    const float* w_hh0  = (const float*)d_in[12];
    const float* b_ih0  = (const float*)d_in[13];
    const float* b_hh0  = (const float*)d_in[14];
    const float* w_ih_r = (const float*)d_in[15];
    const float* w_hh_r = (const float*)d_in[16];
    const float* b_ih_r = (const float*)d_in[17];
    const float* b_hh_r = (const float*)d_in[18];
    const float* fcw    = (const float*)d_in[19];
    const float* fcb    = (const float*)d_in[20];

    float* out     = (float*)d_out;
    float* pred    = out;               // [B, OUT]
    float* hid_out = out + B_ * OUT_;   // [L, B, H]

    float *Wh, *rnn, *energy, *gi, *gh;
    cudaGetSymbolAddress((void**)&Wh,     g_Wh);
    cudaGetSymbolAddress((void**)&rnn,    g_rnn);
    cudaGetSymbolAddress((void**)&energy, g_energy);
    cudaGetSymbolAddress((void**)&gi,     g_gi);
    cudaGetSymbolAddress((void**)&gh,     g_gh);

    const float* hlast = hidden + (size_t)(L_ - 1) * B_ * H_;

    // 1) Wh = hidden[-1] @ Ww^T + Wb   [512x512x512]
    gemm2_kernel<<<dim3(H_ / 128, B_ / 128, 1), 256>>>(
        hlast, Ww, Wb, Wh, H_, hlast, Ww, Wb, Wh, H_, H_);

    // 2) embedding gather
    emb_kernel<<<B_, E_>>>(x, emb, rnn);

    // 3) fused energy (tensor-core GEMM + tanh + aw-reduction)
    energy_mma_kernel<<<(S_ * B_) / 128, 256>>>(Es, Uw, Ub, Wh, aw, ab, energy);

    // 4) softmax over S
    softmax_kernel<<<B_, S_>>>(energy);

    // 5) context -> rnn[:, 0:H]
    context_kernel<<<dim3(H_ / 128, B_), 128>>>(energy, Es, rnn);

    // 6) GRU layer 0: gi and gh in one launch (gridDim.z = 2)
    gemm2_kernel<<<dim3(3 * H_ / 128, B_ / 128, 2), 256>>>(
        rnn, w_ih0, b_ih0, gi, H_ + E_,
        hidden, w_hh0, b_hh0, gh, H_,
        3 * H_);
    gate_kernel<<<(B_ * H_) / 256, 256>>>(gi, gh, hidden, hid_out);

    // 7) GRU layers 1..3
    for (int l = 1; l < L_; l++) {
        const float* wih = w_ih_r + (size_t)(l - 1) * 3 * H_ * H_;
        const float* whh = w_hh_r + (size_t)(l - 1) * 3 * H_ * H_;
        const float* bih = b_ih_r + (size_t)(l - 1) * 3 * H_;
        const float* bhh = b_hh_r + (size_t)(l - 1) * 3 * H_;
        const float* hin = hid_out + (size_t)(l - 1) * B_ * H_;
        const float* hpv = hidden + (size_t)l * B_ * H_;
        gemm2_kernel<<<dim3(3 * H_ / 128, B_ / 128, 2), 256>>>(
            hin, wih, bih, gi, H_,
            hpv, whh, bhh, gh, H_,
            3 * H_);
        gate_kernel<<<(B_ * H_) / 256, 256>>>(gi, gh, hpv, hid_out + (size_t)l * B_ * H_);
    }

    // 8) predictions = h_last @ fcw^T + fcb   [512x128x512]
    gemm2_kernel<<<dim3(OUT_ / 128, B_ / 128, 1), 256>>>(
        hid_out + (size_t)(L_ - 1) * B_ * H_, fcw, fcb, pred, H_,
        hid_out + (size_t)(L_ - 1) * B_ * H_, fcw, fcb, pred, H_,
        OUT_);
}

// round 4
// speedup vs baseline: 5.5015x; 1.5182x over previous
#include <cuda_runtime.h>
#include <cuda_fp16.h>
#include <math.h>
#include <stdint.h>

#define S_   256
#define B_   512
#define H_   512
#define E_   256
#define L_   4
#define OUT_ 128

// ---------------- scratch (no allocs allowed) ----------------
__device__ float g_Wh[B_ * H_];
__device__ float g_rnn[B_ * (H_ + E_)];
__device__ float g_energy[S_ * B_];
__device__ float g_gi[B_ * 3 * H_];
__device__ float g_gh[B_ * 3 * H_];

// ---------------- helpers ----------------
__device__ __forceinline__ uint32_t smem_u32(const void* p) {
    uint32_t a;
    asm("{ .reg .u64 t; cvta.to.shared.u64 t, %1; cvt.u32.u64 %0, t; }" : "=r"(a) : "l"(p));
    return a;
}

__device__ __forceinline__ void ldsm4(uint32_t* r, uint32_t addr) {
    asm volatile("ldmatrix.sync.aligned.m8n8.x4.shared.b16 {%0,%1,%2,%3}, [%4];"
                 : "=r"(r[0]), "=r"(r[1]), "=r"(r[2]), "=r"(r[3]) : "r"(addr));
}

__device__ __forceinline__ void mma16816(float* c, const uint32_t* a, uint32_t b0, uint32_t b1) {
    asm volatile(
        "mma.sync.aligned.m16n8k16.row.col.f32.f16.f16.f32 "
        "{%0,%1,%2,%3}, {%4,%5,%6,%7}, {%8,%9}, {%0,%1,%2,%3};\n"
        : "+f"(c[0]), "+f"(c[1]), "+f"(c[2]), "+f"(c[3])
        : "r"(a[0]), "r"(a[1]), "r"(a[2]), "r"(a[3]), "r"(b0), "r"(b1));
}

// gmem -> regs: N_ float4 per thread, rows of a [*,K] row-major matrix, k-chunk kt*16
template<int N_, int THREADS>
__device__ __forceinline__ void ldg_tile(float4* r, const float* __restrict__ base,
                                         int row0, int K, int kt, int tid) {
#pragma unroll
    for (int i = 0; i < N_; i++) {
        int idx = i * THREADS + tid;
        r[i] = *(const float4*)&base[(size_t)(row0 + (idx >> 2)) * K + kt * 16 + (idx & 3) * 4];
    }
}

// regs -> smem (fp16, 48B-strided rows: 16 halves data + 8 pad)
template<int N_, int THREADS>
__device__ __forceinline__ void sts_tile(const float4* r, __half* dst, int tid) {
#pragma unroll
    for (int i = 0; i < N_; i++) {
        int idx = i * THREADS + tid;
        __half2* d = (__half2*)(dst + (idx >> 2) * 24 + (idx & 3) * 4);
        d[0] = __float22half2_rn(make_float2(r[i].x, r[i].y));
        d[1] = __float22half2_rn(make_float2(r[i].z, r[i].w));
    }
}

// ---------------- fp16 GEMM mainloop ----------------
// Block tile BM x BN, warp tile 64x64, warps = (BM/64)*(BN/64), double-buffered.
// A: rows [row0, row0+BM) of A[*,K]; W: rows [n0, n0+BN) of W[*,K] (output cols).
template<int BM, int BN>
__device__ __forceinline__ void hgemm_loop(float acc[4][8][4],
                                           const float* __restrict__ A,
                                           const float* __restrict__ W,
                                           int row0, int n0, int K,
                                           __half* sA, __half* sW) {
    constexpr int THREADS = (BM / 64) * (BN / 64) * 32;
    constexpr int NA = (BM * 4) / THREADS;
    constexpr int NB = (BN * 4) / THREADS;
    constexpr int WNC = BN / 64;

    const int tid = threadIdx.x;
    const int lane = tid & 31, wid = tid >> 5;
    const int wm = wid / WNC, wn = wid % WNC;
    const int lr = (lane & 7) + ((lane >> 3) & 1) * 8;  // row within 16-row tile
    const int lb = ((lane >> 4) & 1) * 16;              // byte offset (k half)
    const uint32_t aBase = smem_u32(sA);
    const uint32_t wBase = smem_u32(sW);

    float4 ra[NA], rw[NB];
    ldg_tile<NA, THREADS>(ra, A, row0, K, 0, tid);
    ldg_tile<NB, THREADS>(rw, W, n0, K, 0, tid);
    sts_tile<NA, THREADS>(ra, sA, tid);
    sts_tile<NB, THREADS>(rw, sW, tid);
    __syncthreads();

    const int nk = K / 16;
    for (int kt = 0; kt < nk; kt++) {
        const int p = kt & 1;
        if (kt + 1 < nk) {
            ldg_tile<NA, THREADS>(ra, A, row0, K, kt + 1, tid);
            ldg_tile<NB, THREADS>(rw, W, n0, K, kt + 1, tid);
        }
        // fragments from buffer p
        const uint32_t aOff = aBase + (uint32_t)p * BM * 48;
        const uint32_t wOff = wBase + (uint32_t)p * BN * 48;
        uint32_t af[4][4], bt[4][4];
#pragma unroll
        for (int mi = 0; mi < 4; mi++)
            ldsm4(af[mi], aOff + (uint32_t)(wm * 64 + mi * 16 + lr) * 48 + lb);
#pragma unroll
        for (int nt = 0; nt < 4; nt++)
            ldsm4(bt[nt], wOff + (uint32_t)(wn * 64 + nt * 16 + lr) * 48 + lb);
#pragma unroll
        for (int mi = 0; mi < 4; mi++)
#pragma unroll
            for (int ni = 0; ni < 8; ni++) {
                const int nt = ni >> 1, sub = ni & 1;
                mma16816(acc[mi][ni], af[mi], bt[nt][sub ? 1 : 0], bt[nt][sub ? 3 : 2]);
            }
        if (kt + 1 < nk) {
            sts_tile<NA, THREADS>(ra, sA + (p ^ 1) * BM * 24, tid);
            sts_tile<NB, THREADS>(rw, sW + (p ^ 1) * BN * 24, tid);
        }
        __syncthreads();
    }
}

// ---------------- fused energy kernel ----------------
// energy[r] = ab + sum_o aw[o]*tanh( Es[r,:]@Uw[o,:] + Ub[o] + Wh[r&511, o] )
__global__ void __launch_bounds__(256, 1) energy_hmma_kernel(
    const float* __restrict__ Es, const float* __restrict__ Uw,
    const float* __restrict__ Ub, const float* __restrict__ Wh,
    const float* __restrict__ aw, const float* __restrict__ ab,
    float* __restrict__ energy) {
    __shared__ __align__(16) __half sA[2 * 128 * 24];
    __shared__ __align__(16) __half sW[2 * 256 * 24];
    __shared__ float esum[128];

    const int tid = threadIdx.x;
    const int lane = tid & 31, wid = tid >> 5;
    const int wm = wid >> 2, wn = wid & 3;
    const int g = lane >> 2, tg = lane & 3;
    const int r0 = blockIdx.x * 128;
    const int b0 = r0 & (B_ - 1);

    if (tid < 128) esum[tid] = 0.f;

    for (int nc = 0; nc < 2; nc++) {
        float acc[4][8][4] = {};
        hgemm_loop<128, 256>(acc, Es, Uw, r0, nc * 256, H_, sA, sW);

#pragma unroll
        for (int mi = 0; mi < 4; mi++)
#pragma unroll
            for (int hf = 0; hf < 2; hf++) {
                const int rl = wm * 64 + mi * 16 + g + hf * 8;
                const float* WhR = Wh + (size_t)(b0 + rl) * H_;
                float s = 0.f;
#pragma unroll
                for (int ni = 0; ni < 8; ni++) {
                    const int col = nc * 256 + wn * 64 + ni * 8 + tg * 2;
                    float v0 = acc[mi][ni][hf * 2 + 0] + Ub[col] + WhR[col];
                    float v1 = acc[mi][ni][hf * 2 + 1] + Ub[col + 1] + WhR[col + 1];
                    s += tanhf(v0) * aw[col] + tanhf(v1) * aw[col + 1];
                }
                s += __shfl_xor_sync(0xffffffffu, s, 1);
                s += __shfl_xor_sync(0xffffffffu, s, 2);
                if (tg == 0) atomicAdd(&esum[rl], s);
            }
        __syncthreads();
    }
    if (tid < 128) energy[r0 + tid] = esum[tid] + ab[0];
}

// ---------------- generic fp16 GEMM (+bias), 2 jobs via gridDim.z ----------------
template<int BM, int BN>
__global__ void __launch_bounds__((BM / 64) * (BN / 64) * 32, 1) hgemm2_kernel(
    const float* __restrict__ A0, const float* __restrict__ W0,
    const float* __restrict__ bias0, float* __restrict__ C0, int K0,
    const float* __restrict__ A1, const float* __restrict__ W1,
    const float* __restrict__ bias1, float* __restrict__ C1, int K1,
    int N) {
    __shared__ __align__(16) __half sA[2 * BM * 24];
    __shared__ __align__(16) __half sW[2 * BN * 24];

    const float *A, *W, *bias;
    float* C;
    int K;
    if (blockIdx.z == 0) { A = A0; W = W0; bias = bias0; C = C0; K = K0; }
    else                 { A = A1; W = W1; bias = bias1; C = C1; K = K1; }

    const int tid = threadIdx.x;
    const int lane = tid & 31, wid = tid >> 5;
    constexpr int WNC = BN / 64;
    const int wm = wid / WNC, wn = wid % WNC;
    const int g = lane >> 2, tg = lane & 3;
    const int m0 = blockIdx.y * BM;
    const int n0 = blockIdx.x * BN;

    float acc[4][8][4] = {};
    hgemm_loop<BM, BN>(acc, A, W, m0, n0, K, sA, sW);

#pragma unroll
    for (int mi = 0; mi < 4; mi++)
#pragma unroll
        for (int hf = 0; hf < 2; hf++) {
            const int row = m0 + wm * 64 + mi * 16 + g + hf * 8;
#pragma unroll
            for (int ni = 0; ni < 8; ni++) {
                const int col = n0 + wn * 64 + ni * 8 + tg * 2;
                float2 o;
                o.x = acc[mi][ni][hf * 2 + 0] + bias[col];
                o.y = acc[mi][ni][hf * 2 + 1] + bias[col + 1];
                *(float2*)&C[(size_t)row * N + col] = o;
            }
        }
}

// ---------------- softmax over S (one block per b) ----------------
__global__ void softmax_kernel(float* __restrict__ energy) {
    __shared__ float red[S_];
    const int b = blockIdx.x;
    const int s = threadIdx.x;
    float v = energy[s * B_ + b];
    red[s] = v;
    __syncthreads();
    for (int off = S_ / 2; off; off >>= 1) {
        if (s < off) red[s] = fmaxf(red[s], red[s + off]);
        __syncthreads();
    }
    float m = red[0];
    __syncthreads();
    float ex = __expf(v - m);
    red[s] = ex;
    __syncthreads();
    for (int off = S_ / 2; off; off >>= 1) {
        if (s < off) red[s] += red[s + off];
        __syncthreads();
    }
    energy[s * B_ + b] = ex / red[0];
}

// ---------------- context: rnn[b, 0:H] = sum_s att[s,b] * Es[s,b,:] ----------------
__global__ void context_kernel(const float* __restrict__ att,
                               const float* __restrict__ Es,
                               float* __restrict__ rnn) {
    const int b = blockIdx.y;
    const int h = blockIdx.x * 128 + threadIdx.x;
    float a0 = 0.f, a1 = 0.f, a2 = 0.f, a3 = 0.f;
#pragma unroll 4
    for (int s = 0; s < S_; s += 4) {
        a0 = fmaf(att[(s + 0) * B_ + b], Es[((size_t)(s + 0) * B_ + b) * H_ + h], a0);
        a1 = fmaf(att[(s + 1) * B_ + b], Es[((size_t)(s + 1) * B_ + b) * H_ + h], a1);
        a2 = fmaf(att[(s + 2) * B_ + b], Es[((size_t)(s + 2) * B_ + b) * H_ + h], a2);
        a3 = fmaf(att[(s + 3) * B_ + b], Es[((size_t)(s + 3) * B_ + b) * H_ + h], a3);
    }
    rnn[(size_t)b * (H_ + E_) + h] = (a0 + a1) + (a2 + a3);
}

// ---------------- embedding gather ----------------
__global__ void emb_kernel(const int* __restrict__ x,
                           const float* __restrict__ emb,
                           float* __restrict__ rnn) {
    const int b = blockIdx.x;
    const int e = threadIdx.x;
    rnn[(size_t)b * (H_ + E_) + H_ + e] = emb[(size_t)x[b] * E_ + e];
}

// ---------------- GRU gate fusion ----------------
__global__ void gate_kernel(const float* __restrict__ gi,
                            const float* __restrict__ gh,
                            const float* __restrict__ hprev,
                            float* __restrict__ hnew) {
    const int idx = blockIdx.x * 256 + threadIdx.x;
    const int b = idx >> 9;
    const int o = idx & (H_ - 1);
    const float* gib = gi + (size_t)b * 3 * H_;
    const float* ghb = gh + (size_t)b * 3 * H_;
    float ir = gib[o], iz = gib[o + H_], inn = gib[o + 2 * H_];
    float hr = ghb[o], hz = ghb[o + H_], hn = ghb[o + 2 * H_];
    float r = 1.f / (1.f + __expf(-(ir + hr)));
    float z = 1.f / (1.f + __expf(-(iz + hz)));
    float n = tanhf(fmaf(r, hn, inn));
    float h = hprev[idx];
    hnew[idx] = fmaf(z, h - n, n);
}

// ---------------- launch ----------------
extern "C" void kernel_launch(void* const* d_in, const int* in_sizes, int n_in,
                              void* d_out, int out_size) {
    const int*   x      = (const int*)  d_in[0];
    const float* Es     = (const float*)d_in[1];
    const float* hidden = (const float*)d_in[2];
    const float* emb    = (const float*)d_in[4];
    const float* Uw     = (const float*)d_in[5];
    const float* Ub     = (const float*)d_in[6];
    const float* Ww     = (const float*)d_in[7];
    const float* Wb     = (const float*)d_in[8];
    const float* aw     = (const float*)d_in[9];
    const float* ab     = (const float*)d_in[10];
    const float* w_ih0  = (const float*)d_in[11];
    const float* w_hh0  = (const float*)d_in[12];
    const float* b_ih0  = (const float*)d_in[13];
    const float* b_hh0  = (const float*)d_in[14];
    const float* w_ih_r = (const float*)d_in[15];
    const float* w_hh_r = (const float*)d_in[16];
    const float* b_ih_r = (const float*)d_in[17];
    const float* b_hh_r = (const float*)d_in[18];
    const float* fcw    = (const float*)d_in[19];
    const float* fcb    = (const float*)d_in[20];

    float* out     = (float*)d_out;
    float* pred    = out;               // [B, OUT]
    float* hid_out = out + B_ * OUT_;   // [L, B, H]

    float *Wh, *rnn, *energy, *gi, *gh;
    cudaGetSymbolAddress((void**)&Wh,     g_Wh);
    cudaGetSymbolAddress((void**)&rnn,    g_rnn);
    cudaGetSymbolAddress((void**)&energy, g_energy);
    cudaGetSymbolAddress((void**)&gi,     g_gi);
    cudaGetSymbolAddress((void**)&gh,     g_gh);

    const float* hlast = hidden + (size_t)(L_ - 1) * B_ * H_;

    // 1) Wh = hidden[-1] @ Ww^T + Wb   [512x512x512]
    hgemm2_kernel<128, 128><<<dim3(H_ / 128, B_ / 128, 1), 128>>>(
        hlast, Ww, Wb, Wh, H_, hlast, Ww, Wb, Wh, H_, H_);

    // 2) embedding gather
    emb_kernel<<<B_, E_>>>(x, emb, rnn);

    // 3) fused energy (fp16 tensor-core GEMM + tanh + aw-reduction)
    energy_hmma_kernel<<<(S_ * B_) / 128, 256>>>(Es, Uw, Ub, Wh, aw, ab, energy);

    // 4) softmax over S
    softmax_kernel<<<B_, S_>>>(energy);

    // 5) context -> rnn[:, 0:H]
    context_kernel<<<dim3(H_ / 128, B_), 128>>>(energy, Es, rnn);

    // 6) GRU layer 0: gi and gh in one launch (gridDim.z = 2)
    hgemm2_kernel<128, 128><<<dim3(3 * H_ / 128, B_ / 128, 2), 128>>>(
        rnn, w_ih0, b_ih0, gi, H_ + E_,
        hidden, w_hh0, b_hh0, gh, H_,
        3 * H_);
    gate_kernel<<<(B_ * H_) / 256, 256>>>(gi, gh, hidden, hid_out);

    // 7) GRU layers 1..3
    for (int l = 1; l < L_; l++) {
        const float* wih = w_ih_r + (size_t)(l - 1) * 3 * H_ * H_;
        const float* whh = w_hh_r + (size_t)(l - 1) * 3 * H_ * H_;
        const float* bih = b_ih_r + (size_t)(l - 1) * 3 * H_;
        const float* bhh = b_hh_r + (size_t)(l - 1) * 3 * H_;
        const float* hin = hid_out + (size_t)(l - 1) * B_ * H_;
        const float* hpv = hidden + (size_t)l * B_ * H_;
        hgemm2_kernel<128, 128><<<dim3(3 * H_ / 128, B_ / 128, 2), 128>>>(
            hin, wih, bih, gi, H_,
            hpv, whh, bhh, gh, H_,
            3 * H_);
        gate_kernel<<<(B_ * H_) / 256, 256>>>(gi, gh, hpv, hid_out + (size_t)l * B_ * H_);
    }

    // 8) predictions = h_last @ fcw^T + fcb   [512x128x512]
    hgemm2_kernel<128, 128><<<dim3(OUT_ / 128, B_ / 128, 1), 128>>>(
        hid_out + (size_t)(L_ - 1) * B_ * H_, fcw, fcb, pred, H_,
        hid_out + (size_t)(L_ - 1) * B_ * H_, fcw, fcb, pred, H_,
        OUT_);
}